// round 8
// baseline (speedup 1.0000x reference)
#include <cuda_runtime.h>
#include <math.h>

#define B_  32
#define NH  778
#define NO  3000
#define Z_  64
#define NPRIOR 204

#define OBJ_SEGS    4
#define OBJ_SEGLEN  200
#define OBJ_CHUNKS  6
#define OBJ_ITEMS   (OBJ_SEGS * OBJ_CHUNKS * B_)    // 768
#define PRIOR_PAD   208
#define PRIOR_ITEMS (OBJ_CHUNKS * B_)               // 192
#define HAND_TSEG   12
#define HAND_SEGLEN 250
#define HAND_QCH    2
#define HAND_ITEMS  (HAND_TSEG * HAND_QCH * B_)     // 768
#define TOTAL_ITEMS (OBJ_ITEMS + PRIOR_ITEMS + HAND_ITEMS)  // 1728

// ---- epilogue partition: one item per thread, single wave ----
#define EPI_OBJ_BLOCKS  375     // 375*256 = 96000 = B_*NO exactly
#define EPI_HAND_BLOCKS 98      // 98*256 = 25088 >= 24896
#define EPI_MSE_BLOCKS  73      // float4 items: 18672 <= 73*256
#define EPI_KLD_BLOCKS  8       // 2048 = B_*Z_ exactly
#define EPI_TOTAL (EPI_OBJ_BLOCKS + EPI_HAND_BLOCKS + EPI_MSE_BLOCKS + EPI_KLD_BLOCKS) // 554

__device__ unsigned g_okr[OBJ_SEGS][B_ * NO];
__device__ unsigned g_okg[OBJ_SEGS][B_ * NO];
__device__ float    g_mp[B_ * NO];
__device__ float    g_mr[HAND_TSEG][B_ * NH];
__device__ float    g_mg[HAND_TSEG][B_ * NH];
__device__ float    g_epart[EPI_TOTAL][8];
__device__ unsigned g_ctr;

__constant__ int c_prior[NPRIOR] = {
  697,698,699,700,712,713,714,715,737,738,739,740,741,743,744,745,
  746,748,749,750,753,754,755,756,757,758,759,760,761,762,763,764,
  765,766,767,768,
  46,47,48,49,164,165,166,167,194,195,223,237,238,280,281,298,
  301,317,320,323,324,325,326,327,328,329,330,331,332,333,340,341,
  342,343,344,345,346,347,348,349,350,351,352,353,354,355,
  356,357,358,359,375,376,386,387,396,397,402,403,413,429,433,434,
  435,436,437,438,439,440,441,442,443,444,452,453,454,455,456,459,
  460,461,462,463,464,465,466,467,
  468,469,470,471,484,485,486,496,497,506,507,513,514,524,545,546,
  547,548,549,550,551,552,553,555,563,564,565,566,567,570,572,573,
  574,575,576,577,578,
  580,581,582,583,600,601,602,614,615,624,625,630,631,641,663,664,
  665,666,667,668,670,672,680,681,682,683,684,686,687,688,689,690,
  691,692,693,694,695,
  73,96,98,99,772,774,775,777
};

typedef unsigned long long u64;

__device__ __forceinline__ u64 fma2(u64 a, u64 b, u64 c) {
    u64 d;
    asm("fma.rn.f32x2 %0, %1, %2, %3;" : "=l"(d) : "l"(a), "l"(b), "l"(c));
    return d;
}
__device__ __forceinline__ u64 add2(u64 a, u64 b) {
    u64 d;
    asm("add.rn.f32x2 %0, %1, %2;" : "=l"(d) : "l"(a), "l"(b));
    return d;
}
__device__ __forceinline__ u64 pack2(float lo, float hi) {
    u64 d;
    asm("mov.b64 %0, {%1, %2};" : "=l"(d) : "r"(__float_as_uint(lo)), "r"(__float_as_uint(hi)));
    return d;
}
__device__ __forceinline__ void unpack2u(u64 v, unsigned& lo, unsigned& hi) {
    asm("mov.b64 {%0, %1}, %2;" : "=r"(lo), "=r"(hi) : "l"(v));
}
__device__ __forceinline__ float warp_sum(float v) {
#pragma unroll
    for (int o = 16; o > 0; o >>= 1) v += __shfl_down_sync(0xffffffffu, v, o);
    return v;
}
__device__ __forceinline__ float sgnf(float x) {
    return (x > 0.f) ? 1.f : ((x < 0.f) ? -1.f : 0.f);
}

__global__ void __launch_bounds__(256, 4) k_main(
    const float* __restrict__ recon, const float* __restrict__ gt,
    const float* __restrict__ obj)
{
    __shared__ __align__(16) u64 T[HAND_SEGLEN][4];
    const int tid = threadIdx.x;
    const float FINF = __int_as_float(0x7F800000);
    const int item = blockIdx.x;

    if (item < OBJ_ITEMS) {
        const int seg   = item & 3;
        const int rest  = item >> 2;
        const int chunk = rest % OBJ_CHUNKS;
        const int b     = rest / OBJ_CHUNKS;
        const int j0 = chunk * 512 + tid;
        const int j1 = j0 + 256;
        const bool a0 = (j0 < NO), a1 = (j1 < NO);
        const int jj0 = a0 ? j0 : (NO - 1);
        const int jj1 = a1 ? j1 : (NO - 1);

        const float* ob = obj + (size_t)b * NO * 3;
        const float ox0 = ob[3*jj0], oy0 = ob[3*jj0+1], oz0 = ob[3*jj0+2];
        const float ox1 = ob[3*jj1], oy1 = ob[3*jj1+1], oz1 = ob[3*jj1+2];
        const float bq0 = 0.5f*(ox0*ox0 + oy0*oy0 + oz0*oz0);
        const float bq1 = 0.5f*(ox1*ox1 + oy1*oy1 + oz1*oz1);

        const u64 BQ0 = pack2(bq0, bq0), NX0 = pack2(-ox0, -ox0),
                  NY0 = pack2(-oy0, -oy0), NZ0 = pack2(-oz0, -oz0);
        const u64 BQ1 = pack2(bq1, bq1), NX1 = pack2(-ox1, -ox1),
                  NY1 = pack2(-oy1, -oy1), NZ1 = pack2(-oz1, -oz1);

        const float* rb = recon + (size_t)b * NH * 3;
        const float* gb = gt    + (size_t)b * NH * 3;
        const int t0 = seg * OBJ_SEGLEN;

        if (tid < OBJ_SEGLEN) {
            const int tg = t0 + tid;
            float rx=0.f, ry=0.f, rz=0.f, rw=FINF, gx=0.f, gy=0.f, gz=0.f, gw=FINF;
            if (tg < NH) {
                rx = rb[3*tg]; ry = rb[3*tg+1]; rz = rb[3*tg+2];
                rw = 0.5f*(rx*rx + ry*ry + rz*rz);
                gx = gb[3*tg]; gy = gb[3*tg+1]; gz = gb[3*tg+2];
                gw = 0.5f*(gx*gx + gy*gy + gz*gz);
            }
            float2* pp = (float2*)T[tid];
            pp[0] = make_float2(rx, gx); pp[1] = make_float2(ry, gy);
            pp[2] = make_float2(rz, gz); pp[3] = make_float2(rw, gw);
        }
        __syncthreads();

        unsigned br0 = 0xFFFFFFFFu, bg0 = 0xFFFFFFFFu;
        unsigned br1 = 0xFFFFFFFFu, bg1 = 0xFFFFFFFFu;
#pragma unroll 8
        for (int k = 0; k < OBJ_SEGLEN; k++) {
            const ulonglong2 A  = *(const ulonglong2*)&T[k][0];
            const ulonglong2 Bv = *(const ulonglong2*)&T[k][2];
            const unsigned kb = (unsigned)(t0 + k);
            u64 M = add2(BQ0, Bv.y);
            M = fma2(NX0, A.x, M); M = fma2(NY0, A.y, M); M = fma2(NZ0, Bv.x, M);
            unsigned mr, mg; unpack2u(M, mr, mg);
            br0 = min(br0, (mr & 0xFFFFFC00u) | kb);
            bg0 = min(bg0, (mg & 0xFFFFFC00u) | kb);
            M = add2(BQ1, Bv.y);
            M = fma2(NX1, A.x, M); M = fma2(NY1, A.y, M); M = fma2(NZ1, Bv.x, M);
            unpack2u(M, mr, mg);
            br1 = min(br1, (mr & 0xFFFFFC00u) | kb);
            bg1 = min(bg1, (mg & 0xFFFFFC00u) | kb);
        }
        if (a0) { g_okr[seg][b * NO + j0] = br0; g_okg[seg][b * NO + j0] = bg0; }
        if (a1) { g_okr[seg][b * NO + j1] = br1; g_okg[seg][b * NO + j1] = bg1; }
    } else if (item < OBJ_ITEMS + PRIOR_ITEMS) {
        const int idx   = item - OBJ_ITEMS;
        const int chunk = idx % OBJ_CHUNKS;
        const int b     = idx / OBJ_CHUNKS;
        const int j0 = chunk * 512 + tid;
        const int j1 = j0 + 256;
        const bool a0 = (j0 < NO), a1 = (j1 < NO);
        const int jj0 = a0 ? j0 : (NO - 1);
        const int jj1 = a1 ? j1 : (NO - 1);

        const float* ob = obj + (size_t)b * NO * 3;
        const float ox0 = ob[3*jj0], oy0 = ob[3*jj0+1], oz0 = ob[3*jj0+2];
        const float ox1 = ob[3*jj1], oy1 = ob[3*jj1+1], oz1 = ob[3*jj1+2];
        const float bq0 = 0.5f*(ox0*ox0 + oy0*oy0 + oz0*oz0);
        const float bq1 = 0.5f*(ox1*ox1 + oy1*oy1 + oz1*oz1);
        const u64 BQP = pack2(bq0, bq1), NXP = pack2(-ox0, -ox1),
                  NYP = pack2(-oy0, -oy1), NZP = pack2(-oz0, -oz1);

        const float* rb = recon + (size_t)b * NH * 3;
        if (tid < PRIOR_PAD) {
            float x = 0.f, y = 0.f, z = 0.f, w = FINF;
            if (tid < NPRIOR) {
                const int p = c_prior[tid];
                x = rb[3*p]; y = rb[3*p+1]; z = rb[3*p+2];
                w = 0.5f*(x*x + y*y + z*z);
            }
            float2* pp = (float2*)T[tid];
            pp[0] = make_float2(x, x); pp[1] = make_float2(y, y);
            pp[2] = make_float2(z, z); pp[3] = make_float2(w, w);
        }
        __syncthreads();

        float mp0 = FINF, mp1 = FINF;
#pragma unroll 8
        for (int k = 0; k < PRIOR_PAD; k++) {
            const ulonglong2 A  = *(const ulonglong2*)&T[k][0];
            const ulonglong2 Bv = *(const ulonglong2*)&T[k][2];
            u64 M = add2(BQP, Bv.y);
            M = fma2(NXP, A.x, M); M = fma2(NYP, A.y, M); M = fma2(NZP, Bv.x, M);
            unsigned u0, u1; unpack2u(M, u0, u1);
            mp0 = fminf(mp0, __uint_as_float(u0));
            mp1 = fminf(mp1, __uint_as_float(u1));
        }
        if (a0) g_mp[b * NO + j0] = mp0;
        if (a1) g_mp[b * NO + j1] = mp1;
    } else {
        const int idx  = item - OBJ_ITEMS - PRIOR_ITEMS;
        const int ts   = idx % HAND_TSEG;
        const int rest = idx / HAND_TSEG;
        const int qc   = rest % HAND_QCH;
        const int b    = rest / HAND_QCH;
        const int i0 = qc * 512 + tid;
        const int i1 = i0 + 256;
        const bool a0 = (i0 < NH), a1 = (i1 < NH);
        const int ii0 = a0 ? i0 : (NH - 1);
        const int ii1 = a1 ? i1 : (NH - 1);

        const float* rb = recon + (size_t)b * NH * 3;
        const float* gb = gt    + (size_t)b * NH * 3;
        const float rx0 = rb[3*ii0], ry0 = rb[3*ii0+1], rz0 = rb[3*ii0+2];
        const float gx0 = gb[3*ii0], gy0 = gb[3*ii0+1], gz0 = gb[3*ii0+2];
        const float rx1 = rb[3*ii1], ry1 = rb[3*ii1+1], rz1 = rb[3*ii1+2];
        const float gx1 = gb[3*ii1], gy1 = gb[3*ii1+1], gz1 = gb[3*ii1+2];

        const u64 BQ0 = pack2(0.5f*(rx0*rx0+ry0*ry0+rz0*rz0), 0.5f*(gx0*gx0+gy0*gy0+gz0*gz0));
        const u64 NX0 = pack2(-rx0, -gx0), NY0 = pack2(-ry0, -gy0), NZ0 = pack2(-rz0, -gz0);
        const u64 BQ1 = pack2(0.5f*(rx1*rx1+ry1*ry1+rz1*rz1), 0.5f*(gx1*gx1+gy1*gy1+gz1*gz1));
        const u64 NX1 = pack2(-rx1, -gx1), NY1 = pack2(-ry1, -gy1), NZ1 = pack2(-rz1, -gz1);

        const float* obp = obj + (size_t)b * NO * 3 + (size_t)ts * HAND_SEGLEN * 3;
        if (tid < HAND_SEGLEN) {
            float x = obp[3*tid], y = obp[3*tid+1], z = obp[3*tid+2];
            float w = 0.5f*(x*x + y*y + z*z);
            float2* pp = (float2*)T[tid];
            pp[0] = make_float2(x, x); pp[1] = make_float2(y, y);
            pp[2] = make_float2(z, z); pp[3] = make_float2(w, w);
        }
        __syncthreads();

        float mr0 = FINF, mg0 = FINF, mr1 = FINF, mg1 = FINF;
#pragma unroll 5
        for (int k = 0; k < HAND_SEGLEN; k++) {
            const ulonglong2 A  = *(const ulonglong2*)&T[k][0];
            const ulonglong2 Bv = *(const ulonglong2*)&T[k][2];
            u64 M = add2(BQ0, Bv.y);
            M = fma2(NX0, A.x, M); M = fma2(NY0, A.y, M); M = fma2(NZ0, Bv.x, M);
            unsigned u0, u1; unpack2u(M, u0, u1);
            mr0 = fminf(mr0, __uint_as_float(u0));
            mg0 = fminf(mg0, __uint_as_float(u1));
            M = add2(BQ1, Bv.y);
            M = fma2(NX1, A.x, M); M = fma2(NY1, A.y, M); M = fma2(NZ1, Bv.x, M);
            unpack2u(M, u0, u1);
            mr1 = fminf(mr1, __uint_as_float(u0));
            mg1 = fminf(mg1, __uint_as_float(u1));
        }
        if (a0) { g_mr[ts][b * NH + i0] = mr0; g_mg[ts][b * NH + i0] = mg0; }
        if (a1) { g_mr[ts][b * NH + i1] = mr1; g_mg[ts][b * NH + i1] = mg1; }
    }
}

// Epilogue: one item per thread, role-partitioned blocks, single wave.
__global__ void __launch_bounds__(256) k_epi(
    const float* __restrict__ recon, const float* __restrict__ gt,
    const float* __restrict__ recon_n, const float* __restrict__ gt_n,
    const float* __restrict__ obj,
    const float* __restrict__ mean, const float* __restrict__ logv,
    const float* __restrict__ vw, float* __restrict__ out)
{
    const int tid = threadIdx.x;
    const int blk = blockIdx.x;

    // a: penetr, n_pts, contact, consist, loss_o, loss_h, mse, kld
    float a[8] = {0.f,0.f,0.f,0.f,0.f,0.f,0.f,0.f};

    if (blk < EPI_OBJ_BLOCKS) {
        const int idx = blk * 256 + tid;     // < 96000 always
        const int b = idx / NO;
        const int j = idx - b * NO;
        const float* ob = obj + (size_t)b * NO * 3;
        const float ox = ob[3*j], oy = ob[3*j+1], oz = ob[3*j+2];
        const unsigned br = min(min(g_okr[0][idx], g_okr[1][idx]),
                                min(g_okr[2][idx], g_okr[3][idx]));
        const unsigned bg = min(min(g_okg[0][idx], g_okg[1][idx]),
                                min(g_okg[2][idx], g_okg[3][idx]));
        const int ir = (int)(br & 1023u);
        const int ig = (int)(bg & 1023u);
        const float mp = g_mp[idx];

        const float* rb  = recon   + (size_t)b * NH * 3;
        const float* gb  = gt      + (size_t)b * NH * 3;
        const float* rnb = recon_n + (size_t)b * NH * 3;
        const float* gnb = gt_n    + (size_t)b * NH * 3;

        float dxr = ox - rb[3*ir], dyr = oy - rb[3*ir+1], dzr = oz - rb[3*ir+2];
        float d2r = dxr*dxr + dyr*dyr + dzr*dzr;
        float dotr = rnb[3*ir]*dxr + rnb[3*ir+1]*dyr + rnb[3*ir+2]*dzr;
        float o2h = sqrtf(d2r) * sgnf(dotr);
        bool interior = (-dotr) > 0.f;

        float dxg = ox - gb[3*ig], dyg = oy - gb[3*ig+1], dzg = oz - gb[3*ig+2];
        float d2g = dxg*dxg + dyg*dyg + dzg*dzg;
        float dotg = gnb[3*ig]*dxg + gnb[3*ig+1]*dyg + gnb[3*ig+2]*dzg;
        float o2h_gt = sqrtf(d2g) * sgnf(dotg);

        float d2p = fmaxf(2.f * mp, 0.f);
        bool cmap  = sqrtf(d2g) < 0.005f;
        bool rcmap = sqrtf(d2r) < 0.005f;

        a[0] = interior ? d2r : 0.f;
        a[1] = cmap ? 1.f : 0.f;
        a[2] = cmap ? d2p : 0.f;
        a[3] = (cmap && rcmap) ? 1.f : 0.f;
        bool w_dist = (o2h_gt < 0.01f) && (o2h_gt > -0.005f);
        float w = (o2h < 0.f) ? 1.5f : (w_dist ? 1.0f : 0.1f);
        a[4] = fabsf(o2h - o2h_gt) * w;
    } else if (blk < EPI_OBJ_BLOCKS + EPI_HAND_BLOCKS) {
        const int j = (blk - EPI_OBJ_BLOCKS) * 256 + tid;
        if (j < B_ * NH) {
            const int i = j % NH;
            float mr = g_mr[0][j], mg = g_mg[0][j];
#pragma unroll
            for (int s = 1; s < HAND_TSEG; s++) {
                mr = fminf(mr, g_mr[s][j]);
                mg = fminf(mg, g_mg[s][j]);
            }
            float dr = sqrtf(fmaxf(2.f * mr, 0.f));
            float dg = sqrtf(fmaxf(2.f * mg, 0.f));
            a[5] = fabsf(dr - dg) * powf(vw[i], 0.4f);
        }
    } else if (blk < EPI_OBJ_BLOCKS + EPI_HAND_BLOCKS + EPI_MSE_BLOCKS) {
        const int q = (blk - EPI_OBJ_BLOCKS - EPI_HAND_BLOCKS) * 256 + tid;
        if (q < (B_ * NH * 3) / 4) {    // 18672 float4 items
            const float4 r4 = ((const float4*)recon)[q];
            const float4 g4 = ((const float4*)gt)[q];
            float d0 = r4.x - g4.x, d1 = r4.y - g4.y, d2 = r4.z - g4.z, d3 = r4.w - g4.w;
            a[6] = d0*d0 + d1*d1 + d2*d2 + d3*d3;
        }
    } else {
        const int q = (blk - EPI_OBJ_BLOCKS - EPI_HAND_BLOCKS - EPI_MSE_BLOCKS) * 256 + tid;
        // q < 2048 = B_*Z_ exactly
        float m = mean[q], lv = logv[q];
        a[7] = 1.f + lv - m * m - expf(lv);
    }

    __shared__ float red[8][8];
    __shared__ bool s_last;
    const int lane = tid & 31, warp = tid >> 5;
#pragma unroll
    for (int q = 0; q < 8; q++) {
        float v = warp_sum(a[q]);
        if (lane == 0) red[warp][q] = v;
    }
    __syncthreads();
    if (tid < 8) {
        float s = 0.f;
#pragma unroll
        for (int wi = 0; wi < 8; wi++) s += red[wi][tid];
        g_epart[blk][tid] = s;
    }
    if (tid == 0) {
        __threadfence();
        unsigned t = atomicAdd(&g_ctr, 1u);
        s_last = (t == (unsigned)(gridDim.x - 1));
    }
    __syncthreads();

    if (s_last) {
        __threadfence();
        float p[8] = {0.f,0.f,0.f,0.f,0.f,0.f,0.f,0.f};
        for (int i = tid; i < EPI_TOTAL; i += 256) {
#pragma unroll
            for (int q = 0; q < 8; q++) p[q] += g_epart[i][q];
        }
#pragma unroll
        for (int q = 0; q < 8; q++) {
            float v = warp_sum(p[q]);
            if (lane == 0) red[warp][q] = v;
        }
        __syncthreads();
        if (tid == 0) {
            double acc[8];
#pragma unroll
            for (int q = 0; q < 8; q++) {
                float s = 0.f;
                for (int wi = 0; wi < 8; wi++) s += red[wi][q];
                acc[q] = (double)s;
            }
            const double KLC = 0.005;
            double recon_loss = acc[6] / B_;
            double kld        = -0.5 * acc[7] / B_ * 10.0;
            double penetr     = 100.0 * acc[0] / B_;
            double npts       = acc[1];
            double contact    = 3000.0 * ((npts > 0.0) ? (acc[2] / (B_ * npts)) : 0.0);
            double consist    = -5.0 * acc[3] / (npts + 0.0001);
            double loss_o     = 30.0 * (1.0 - KLC) * acc[4] / ((double)B_ * NO);
            double loss_h     = 35.0 * (1.0 - KLC) * acc[5] / ((double)B_ * NH);
            double total = recon_loss + 0.1 * kld + 1000.0 * penetr
                         + 10.0 * contact + 10.0 * consist + (loss_h + loss_o);
            out[0] = (float)total;
            g_ctr = 0u;
        }
    }
}

extern "C" void kernel_launch(void* const* d_in, const int* in_sizes, int n_in,
                              void* d_out, int out_size) {
    const float* recon   = (const float*)d_in[0];
    const float* gt      = (const float*)d_in[1];
    const float* recon_n = (const float*)d_in[2];
    const float* gt_n    = (const float*)d_in[3];
    const float* obj     = (const float*)d_in[4];
    const float* mean    = (const float*)d_in[5];
    const float* logv    = (const float*)d_in[6];
    const float* vw      = (const float*)d_in[7];
    float* out = (float*)d_out;

    k_main<<<TOTAL_ITEMS, 256>>>(recon, gt, obj);
    k_epi<<<EPI_TOTAL, 256>>>(recon, gt, recon_n, gt_n, obj, mean, logv, vw, out);
}

// round 9
// speedup vs baseline: 1.2430x; 1.2430x over previous
#include <cuda_runtime.h>
#include <math.h>

#define B_  32
#define NH  778
#define NO  3000
#define Z_  64
#define NPRIOR 204

#define NT_PAD      800        // padded target count (multiple of SEGLEN)
#define FUS_SEGS    8
#define FUS_SEGLEN  100        // 8*100 = 800 >= 778
#define FUS_CHUNKS  6          // 6*512 = 3072 >= 3000 (2 queries/thread)
#define FUS_ITEMS   (FUS_SEGS * FUS_CHUNKS * B_)    // 1536
#define PRIOR_PAD   208
#define PRIOR_ITEMS (FUS_CHUNKS * B_)               // 192
#define TOTAL_ITEMS (FUS_ITEMS + PRIOR_ITEMS)       // 1728

// ---- epilogue partition: one item per thread, single wave ----
#define EPI_OBJ_BLOCKS  375     // 375*256 = 96000 = B_*NO exactly
#define EPI_HAND_BLOCKS 98      // 98*256 = 25088 >= 24896
#define EPI_MSE_BLOCKS  73
#define EPI_KLD_BLOCKS  8
#define EPI_TOTAL (EPI_OBJ_BLOCKS + EPI_HAND_BLOCKS + EPI_MSE_BLOCKS + EPI_KLD_BLOCKS) // 554

__device__ unsigned g_okr[FUS_SEGS][B_ * NO];   // per-seg obj->recon argmin keys
__device__ unsigned g_okg[FUS_SEGS][B_ * NO];   // per-seg obj->gt argmin keys
__device__ float    g_mp[B_ * NO];              // obj->prior min m
__device__ float    g_cmr[FUS_CHUNKS][B_ * NT_PAD];  // per-chunk col-min (recon hands)
__device__ float    g_cmg[FUS_CHUNKS][B_ * NT_PAD];  // per-chunk col-min (gt hands)
__device__ float    g_epart[EPI_TOTAL][8];
__device__ unsigned g_ctr;

__constant__ int c_prior[NPRIOR] = {
  697,698,699,700,712,713,714,715,737,738,739,740,741,743,744,745,
  746,748,749,750,753,754,755,756,757,758,759,760,761,762,763,764,
  765,766,767,768,
  46,47,48,49,164,165,166,167,194,195,223,237,238,280,281,298,
  301,317,320,323,324,325,326,327,328,329,330,331,332,333,340,341,
  342,343,344,345,346,347,348,349,350,351,352,353,354,355,
  356,357,358,359,375,376,386,387,396,397,402,403,413,429,433,434,
  435,436,437,438,439,440,441,442,443,444,452,453,454,455,456,459,
  460,461,462,463,464,465,466,467,
  468,469,470,471,484,485,486,496,497,506,507,513,514,524,545,546,
  547,548,549,550,551,552,553,555,563,564,565,566,567,570,572,573,
  574,575,576,577,578,
  580,581,582,583,600,601,602,614,615,624,625,630,631,641,663,664,
  665,666,667,668,670,672,680,681,682,683,684,686,687,688,689,690,
  691,692,693,694,695,
  73,96,98,99,772,774,775,777
};

typedef unsigned long long u64;

__device__ __forceinline__ u64 fma2(u64 a, u64 b, u64 c) {
    u64 d;
    asm("fma.rn.f32x2 %0, %1, %2, %3;" : "=l"(d) : "l"(a), "l"(b), "l"(c));
    return d;
}
__device__ __forceinline__ u64 add2(u64 a, u64 b) {
    u64 d;
    asm("add.rn.f32x2 %0, %1, %2;" : "=l"(d) : "l"(a), "l"(b));
    return d;
}
__device__ __forceinline__ u64 pack2(float lo, float hi) {
    u64 d;
    asm("mov.b64 %0, {%1, %2};" : "=l"(d) : "r"(__float_as_uint(lo)), "r"(__float_as_uint(hi)));
    return d;
}
__device__ __forceinline__ void unpack2u(u64 v, unsigned& lo, unsigned& hi) {
    asm("mov.b64 {%0, %1}, %2;" : "=r"(lo), "=r"(hi) : "l"(v));
}
__device__ __forceinline__ float warp_sum(float v) {
#pragma unroll
    for (int o = 16; o > 0; o >>= 1) v += __shfl_down_sync(0xffffffffu, v, o);
    return v;
}
__device__ __forceinline__ float sgnf(float x) {
    return (x > 0.f) ? 1.f : ((x < 0.f) ? -1.f : 0.f);
}

__global__ void __launch_bounds__(256, 4) k_main(
    const float* __restrict__ recon, const float* __restrict__ gt,
    const float* __restrict__ obj)
{
    __shared__ __align__(16) u64 T[PRIOR_PAD][4];     // target tile (208 covers both uses)
    __shared__ float s_cmr[8][FUS_SEGLEN];            // per-warp col-mins
    __shared__ float s_cmg[8][FUS_SEGLEN];
    const int tid = threadIdx.x;
    const int lane = tid & 31, warp = tid >> 5;
    const float FINF = __int_as_float(0x7F800000);
    const int item = blockIdx.x;

    if (item < FUS_ITEMS) {
        // ===== FUSED: row argmin (obj->hand) + col min (hand->obj) =====
        const int seg   = item & 7;
        const int rest  = item >> 3;
        const int chunk = rest % FUS_CHUNKS;
        const int b     = rest / FUS_CHUNKS;
        const int j0 = chunk * 512 + tid;
        const int j1 = j0 + 256;
        const bool a0 = (j0 < NO), a1 = (j1 < NO);
        const int jj0 = a0 ? j0 : (NO - 1);
        const int jj1 = a1 ? j1 : (NO - 1);

        const float* ob = obj + (size_t)b * NO * 3;
        const float ox0 = ob[3*jj0], oy0 = ob[3*jj0+1], oz0 = ob[3*jj0+2];
        const float ox1 = ob[3*jj1], oy1 = ob[3*jj1+1], oz1 = ob[3*jj1+2];
        const float bq0 = 0.5f*(ox0*ox0 + oy0*oy0 + oz0*oz0);
        const float bq1 = 0.5f*(ox1*ox1 + oy1*oy1 + oz1*oz1);

        const u64 BQ0 = pack2(bq0, bq0), NX0 = pack2(-ox0, -ox0),
                  NY0 = pack2(-oy0, -oy0), NZ0 = pack2(-oz0, -oz0);
        const u64 BQ1 = pack2(bq1, bq1), NX1 = pack2(-ox1, -ox1),
                  NY1 = pack2(-oy1, -oy1), NZ1 = pack2(-oz1, -oz1);

        const float* rb = recon + (size_t)b * NH * 3;
        const float* gb = gt    + (size_t)b * NH * 3;
        const int t0 = seg * FUS_SEGLEN;

        if (tid < FUS_SEGLEN) {
            const int tg = t0 + tid;
            float rx=0.f, ry=0.f, rz=0.f, rw=FINF, gx=0.f, gy=0.f, gz=0.f, gw=FINF;
            if (tg < NH) {
                rx = rb[3*tg]; ry = rb[3*tg+1]; rz = rb[3*tg+2];
                rw = 0.5f*(rx*rx + ry*ry + rz*rz);
                gx = gb[3*tg]; gy = gb[3*tg+1]; gz = gb[3*tg+2];
                gw = 0.5f*(gx*gx + gy*gy + gz*gz);
            }
            float2* pp = (float2*)T[tid];
            pp[0] = make_float2(rx, gx); pp[1] = make_float2(ry, gy);
            pp[2] = make_float2(rz, gz); pp[3] = make_float2(rw, gw);
        }
        __syncthreads();

        unsigned br0 = 0xFFFFFFFFu, bg0 = 0xFFFFFFFFu;
        unsigned br1 = 0xFFFFFFFFu, bg1 = 0xFFFFFFFFu;
#pragma unroll 4
        for (int k = 0; k < FUS_SEGLEN; k++) {
            const ulonglong2 A  = *(const ulonglong2*)&T[k][0];
            const ulonglong2 Bv = *(const ulonglong2*)&T[k][2];
            const unsigned kb = (unsigned)(t0 + k);
            u64 M0 = add2(BQ0, Bv.y);
            M0 = fma2(NX0, A.x, M0); M0 = fma2(NY0, A.y, M0); M0 = fma2(NZ0, Bv.x, M0);
            unsigned r0, g0; unpack2u(M0, r0, g0);
            br0 = min(br0, (r0 & 0xFFFFFC00u) | kb);
            bg0 = min(bg0, (g0 & 0xFFFFFC00u) | kb);
            u64 M1 = add2(BQ1, Bv.y);
            M1 = fma2(NX1, A.x, M1); M1 = fma2(NY1, A.y, M1); M1 = fma2(NZ1, Bv.x, M1);
            unsigned r1, g1; unpack2u(M1, r1, g1);
            br1 = min(br1, (r1 & 0xFFFFFC00u) | kb);
            bg1 = min(bg1, (g1 & 0xFFFFFC00u) | kb);
            // col-min (hand->obj): min over this warp's queries, clamped >= 0
            float vr = fmaxf(fminf(__uint_as_float(r0), __uint_as_float(r1)), 0.f);
            float vg = fmaxf(fminf(__uint_as_float(g0), __uint_as_float(g1)), 0.f);
            unsigned wr = __reduce_min_sync(0xffffffffu, __float_as_uint(vr));
            unsigned wg = __reduce_min_sync(0xffffffffu, __float_as_uint(vg));
            if (lane == 0) {
                s_cmr[warp][k] = __uint_as_float(wr);
                s_cmg[warp][k] = __uint_as_float(wg);
            }
        }
        if (a0) { g_okr[seg][b * NO + j0] = br0; g_okg[seg][b * NO + j0] = bg0; }
        if (a1) { g_okr[seg][b * NO + j1] = br1; g_okg[seg][b * NO + j1] = bg1; }

        __syncthreads();
        if (tid < FUS_SEGLEN) {
            float mr = s_cmr[0][tid], mg = s_cmg[0][tid];
#pragma unroll
            for (int w = 1; w < 8; w++) {
                mr = fminf(mr, s_cmr[w][tid]);
                mg = fminf(mg, s_cmg[w][tid]);
            }
            g_cmr[chunk][b * NT_PAD + t0 + tid] = mr;
            g_cmg[chunk][b * NT_PAD + t0 + tid] = mg;
        }
    } else {
        // ===== PRIOR: 204 targets, 512 queries =====
        const int idx   = item - FUS_ITEMS;
        const int chunk = idx % FUS_CHUNKS;
        const int b     = idx / FUS_CHUNKS;
        const int j0 = chunk * 512 + tid;
        const int j1 = j0 + 256;
        const bool a0 = (j0 < NO), a1 = (j1 < NO);
        const int jj0 = a0 ? j0 : (NO - 1);
        const int jj1 = a1 ? j1 : (NO - 1);

        const float* ob = obj + (size_t)b * NO * 3;
        const float ox0 = ob[3*jj0], oy0 = ob[3*jj0+1], oz0 = ob[3*jj0+2];
        const float ox1 = ob[3*jj1], oy1 = ob[3*jj1+1], oz1 = ob[3*jj1+2];
        const float bq0 = 0.5f*(ox0*ox0 + oy0*oy0 + oz0*oz0);
        const float bq1 = 0.5f*(ox1*ox1 + oy1*oy1 + oz1*oz1);
        const u64 BQP = pack2(bq0, bq1), NXP = pack2(-ox0, -ox1),
                  NYP = pack2(-oy0, -oy1), NZP = pack2(-oz0, -oz1);

        const float* rb = recon + (size_t)b * NH * 3;
        if (tid < PRIOR_PAD) {
            float x = 0.f, y = 0.f, z = 0.f, w = FINF;
            if (tid < NPRIOR) {
                const int p = c_prior[tid];
                x = rb[3*p]; y = rb[3*p+1]; z = rb[3*p+2];
                w = 0.5f*(x*x + y*y + z*z);
            }
            float2* pp = (float2*)T[tid];
            pp[0] = make_float2(x, x); pp[1] = make_float2(y, y);
            pp[2] = make_float2(z, z); pp[3] = make_float2(w, w);
        }
        __syncthreads();

        float mp0 = FINF, mp1 = FINF;
#pragma unroll 8
        for (int k = 0; k < PRIOR_PAD; k++) {
            const ulonglong2 A  = *(const ulonglong2*)&T[k][0];
            const ulonglong2 Bv = *(const ulonglong2*)&T[k][2];
            u64 M = add2(BQP, Bv.y);
            M = fma2(NXP, A.x, M); M = fma2(NYP, A.y, M); M = fma2(NZP, Bv.x, M);
            unsigned u0, u1; unpack2u(M, u0, u1);
            mp0 = fminf(mp0, __uint_as_float(u0));
            mp1 = fminf(mp1, __uint_as_float(u1));
        }
        if (a0) g_mp[b * NO + j0] = mp0;
        if (a1) g_mp[b * NO + j1] = mp1;
    }
}

// Epilogue: one item per thread, role-partitioned blocks.
__global__ void __launch_bounds__(256) k_epi(
    const float* __restrict__ recon, const float* __restrict__ gt,
    const float* __restrict__ recon_n, const float* __restrict__ gt_n,
    const float* __restrict__ obj,
    const float* __restrict__ mean, const float* __restrict__ logv,
    const float* __restrict__ vw, float* __restrict__ out)
{
    const int tid = threadIdx.x;
    const int blk = blockIdx.x;

    float a[8] = {0.f,0.f,0.f,0.f,0.f,0.f,0.f,0.f};

    if (blk < EPI_OBJ_BLOCKS) {
        const int idx = blk * 256 + tid;
        const int b = idx / NO;
        const int j = idx - b * NO;
        const float* ob = obj + (size_t)b * NO * 3;
        const float ox = ob[3*j], oy = ob[3*j+1], oz = ob[3*j+2];
        unsigned br = g_okr[0][idx], bg = g_okg[0][idx];
#pragma unroll
        for (int s = 1; s < FUS_SEGS; s++) {
            br = min(br, g_okr[s][idx]);
            bg = min(bg, g_okg[s][idx]);
        }
        const int ir = (int)(br & 1023u);
        const int ig = (int)(bg & 1023u);
        const float mp = g_mp[idx];

        const float* rb  = recon   + (size_t)b * NH * 3;
        const float* gb  = gt      + (size_t)b * NH * 3;
        const float* rnb = recon_n + (size_t)b * NH * 3;
        const float* gnb = gt_n    + (size_t)b * NH * 3;

        float dxr = ox - rb[3*ir], dyr = oy - rb[3*ir+1], dzr = oz - rb[3*ir+2];
        float d2r = dxr*dxr + dyr*dyr + dzr*dzr;
        float dotr = rnb[3*ir]*dxr + rnb[3*ir+1]*dyr + rnb[3*ir+2]*dzr;
        float o2h = sqrtf(d2r) * sgnf(dotr);
        bool interior = (-dotr) > 0.f;

        float dxg = ox - gb[3*ig], dyg = oy - gb[3*ig+1], dzg = oz - gb[3*ig+2];
        float d2g = dxg*dxg + dyg*dyg + dzg*dzg;
        float dotg = gnb[3*ig]*dxg + gnb[3*ig+1]*dyg + gnb[3*ig+2]*dzg;
        float o2h_gt = sqrtf(d2g) * sgnf(dotg);

        float d2p = fmaxf(2.f * mp, 0.f);
        bool cmap  = sqrtf(d2g) < 0.005f;
        bool rcmap = sqrtf(d2r) < 0.005f;

        a[0] = interior ? d2r : 0.f;
        a[1] = cmap ? 1.f : 0.f;
        a[2] = cmap ? d2p : 0.f;
        a[3] = (cmap && rcmap) ? 1.f : 0.f;
        bool w_dist = (o2h_gt < 0.01f) && (o2h_gt > -0.005f);
        float w = (o2h < 0.f) ? 1.5f : (w_dist ? 1.0f : 0.1f);
        a[4] = fabsf(o2h - o2h_gt) * w;
    } else if (blk < EPI_OBJ_BLOCKS + EPI_HAND_BLOCKS) {
        const int j = (blk - EPI_OBJ_BLOCKS) * 256 + tid;
        if (j < B_ * NH) {
            const int b = j / NH;
            const int i = j - b * NH;
            const int base = b * NT_PAD + i;
            float mr = g_cmr[0][base], mg = g_cmg[0][base];
#pragma unroll
            for (int c = 1; c < FUS_CHUNKS; c++) {
                mr = fminf(mr, g_cmr[c][base]);
                mg = fminf(mg, g_cmg[c][base]);
            }
            float dr = sqrtf(fmaxf(2.f * mr, 0.f));
            float dg = sqrtf(fmaxf(2.f * mg, 0.f));
            a[5] = fabsf(dr - dg) * powf(vw[i], 0.4f);
        }
    } else if (blk < EPI_OBJ_BLOCKS + EPI_HAND_BLOCKS + EPI_MSE_BLOCKS) {
        const int q = (blk - EPI_OBJ_BLOCKS - EPI_HAND_BLOCKS) * 256 + tid;
        if (q < (B_ * NH * 3) / 4) {
            const float4 r4 = ((const float4*)recon)[q];
            const float4 g4 = ((const float4*)gt)[q];
            float d0 = r4.x - g4.x, d1 = r4.y - g4.y, d2 = r4.z - g4.z, d3 = r4.w - g4.w;
            a[6] = d0*d0 + d1*d1 + d2*d2 + d3*d3;
        }
    } else {
        const int q = (blk - EPI_OBJ_BLOCKS - EPI_HAND_BLOCKS - EPI_MSE_BLOCKS) * 256 + tid;
        float m = mean[q], lv = logv[q];
        a[7] = 1.f + lv - m * m - expf(lv);
    }

    __shared__ float red[8][8];
    __shared__ bool s_last;
    const int lane = tid & 31, warp = tid >> 5;
#pragma unroll
    for (int q = 0; q < 8; q++) {
        float v = warp_sum(a[q]);
        if (lane == 0) red[warp][q] = v;
    }
    __syncthreads();
    if (tid < 8) {
        float s = 0.f;
#pragma unroll
        for (int wi = 0; wi < 8; wi++) s += red[wi][tid];
        g_epart[blk][tid] = s;
    }
    if (tid == 0) {
        __threadfence();
        unsigned t = atomicAdd(&g_ctr, 1u);
        s_last = (t == (unsigned)(gridDim.x - 1));
    }
    __syncthreads();

    if (s_last) {
        __threadfence();
        float p[8] = {0.f,0.f,0.f,0.f,0.f,0.f,0.f,0.f};
        for (int i = tid; i < EPI_TOTAL; i += 256) {
#pragma unroll
            for (int q = 0; q < 8; q++) p[q] += g_epart[i][q];
        }
#pragma unroll
        for (int q = 0; q < 8; q++) {
            float v = warp_sum(p[q]);
            if (lane == 0) red[warp][q] = v;
        }
        __syncthreads();
        if (tid == 0) {
            double acc[8];
#pragma unroll
            for (int q = 0; q < 8; q++) {
                float s = 0.f;
                for (int wi = 0; wi < 8; wi++) s += red[wi][q];
                acc[q] = (double)s;
            }
            const double KLC = 0.005;
            double recon_loss = acc[6] / B_;
            double kld        = -0.5 * acc[7] / B_ * 10.0;
            double penetr     = 100.0 * acc[0] / B_;
            double npts       = acc[1];
            double contact    = 3000.0 * ((npts > 0.0) ? (acc[2] / (B_ * npts)) : 0.0);
            double consist    = -5.0 * acc[3] / (npts + 0.0001);
            double loss_o     = 30.0 * (1.0 - KLC) * acc[4] / ((double)B_ * NO);
            double loss_h     = 35.0 * (1.0 - KLC) * acc[5] / ((double)B_ * NH);
            double total = recon_loss + 0.1 * kld + 1000.0 * penetr
                         + 10.0 * contact + 10.0 * consist + (loss_h + loss_o);
            out[0] = (float)total;
            g_ctr = 0u;
        }
    }
}

extern "C" void kernel_launch(void* const* d_in, const int* in_sizes, int n_in,
                              void* d_out, int out_size) {
    const float* recon   = (const float*)d_in[0];
    const float* gt      = (const float*)d_in[1];
    const float* recon_n = (const float*)d_in[2];
    const float* gt_n    = (const float*)d_in[3];
    const float* obj     = (const float*)d_in[4];
    const float* mean    = (const float*)d_in[5];
    const float* logv    = (const float*)d_in[6];
    const float* vw      = (const float*)d_in[7];
    float* out = (float*)d_out;

    k_main<<<TOTAL_ITEMS, 256>>>(recon, gt, obj);
    k_epi<<<EPI_TOTAL, 256>>>(recon, gt, recon_n, gt_n, obj, mean, logv, vw, out);
}

// round 10
// speedup vs baseline: 1.2435x; 1.0005x over previous
#include <cuda_runtime.h>
#include <math.h>

#define B_  32
#define NH  778
#define NO  3000
#define Z_  64
#define NPRIOR 204

#define NT_PAD      800
#define FUS_SEGS    8
#define FUS_SEGLEN  100
#define FUS_CHUNKS  6          // 6*512 = 3072 >= 3000 (2 queries/thread)
#define FUS_ITEMS   (FUS_SEGS * FUS_CHUNKS * B_)    // 1536
#define PRIOR_PAD   208
#define PRIOR_ITEMS (FUS_CHUNKS * B_)               // 192  (FIRST in grid: longest blocks)
#define TOTAL_ITEMS (FUS_ITEMS + PRIOR_ITEMS)       // 1728

// ---- epilogue: [MSE][KLD][OBJ][HAND] so input-only blocks run under k_main via PDL ----
#define EPI_MSE_BLOCKS  73
#define EPI_KLD_BLOCKS  8
#define EPI_OBJ_BLOCKS  375     // 375*256 = 96000 exactly
#define EPI_HAND_BLOCKS 98
#define EPI_TOTAL (EPI_MSE_BLOCKS + EPI_KLD_BLOCKS + EPI_OBJ_BLOCKS + EPI_HAND_BLOCKS) // 554

__device__ unsigned g_okr[FUS_SEGS][B_ * NO];
__device__ unsigned g_okg[FUS_SEGS][B_ * NO];
__device__ float    g_mp[B_ * NO];
__device__ float    g_cmr[FUS_CHUNKS][B_ * NT_PAD];
__device__ float    g_cmg[FUS_CHUNKS][B_ * NT_PAD];
__device__ float    g_epart[EPI_TOTAL][8];
__device__ unsigned g_ctr;

__constant__ int c_prior[NPRIOR] = {
  697,698,699,700,712,713,714,715,737,738,739,740,741,743,744,745,
  746,748,749,750,753,754,755,756,757,758,759,760,761,762,763,764,
  765,766,767,768,
  46,47,48,49,164,165,166,167,194,195,223,237,238,280,281,298,
  301,317,320,323,324,325,326,327,328,329,330,331,332,333,340,341,
  342,343,344,345,346,347,348,349,350,351,352,353,354,355,
  356,357,358,359,375,376,386,387,396,397,402,403,413,429,433,434,
  435,436,437,438,439,440,441,442,443,444,452,453,454,455,456,459,
  460,461,462,463,464,465,466,467,
  468,469,470,471,484,485,486,496,497,506,507,513,514,524,545,546,
  547,548,549,550,551,552,553,555,563,564,565,566,567,570,572,573,
  574,575,576,577,578,
  580,581,582,583,600,601,602,614,615,624,625,630,631,641,663,664,
  665,666,667,668,670,672,680,681,682,683,684,686,687,688,689,690,
  691,692,693,694,695,
  73,96,98,99,772,774,775,777
};

typedef unsigned long long u64;

__device__ __forceinline__ u64 fma2(u64 a, u64 b, u64 c) {
    u64 d;
    asm("fma.rn.f32x2 %0, %1, %2, %3;" : "=l"(d) : "l"(a), "l"(b), "l"(c));
    return d;
}
__device__ __forceinline__ u64 add2(u64 a, u64 b) {
    u64 d;
    asm("add.rn.f32x2 %0, %1, %2;" : "=l"(d) : "l"(a), "l"(b));
    return d;
}
__device__ __forceinline__ u64 pack2(float lo, float hi) {
    u64 d;
    asm("mov.b64 %0, {%1, %2};" : "=l"(d) : "r"(__float_as_uint(lo)), "r"(__float_as_uint(hi)));
    return d;
}
__device__ __forceinline__ void unpack2u(u64 v, unsigned& lo, unsigned& hi) {
    asm("mov.b64 {%0, %1}, %2;" : "=r"(lo), "=r"(hi) : "l"(v));
}
__device__ __forceinline__ float warp_sum(float v) {
#pragma unroll
    for (int o = 16; o > 0; o >>= 1) v += __shfl_down_sync(0xffffffffu, v, o);
    return v;
}
__device__ __forceinline__ float sgnf(float x) {
    return (x > 0.f) ? 1.f : ((x < 0.f) ? -1.f : 0.f);
}

__global__ void __launch_bounds__(256, 4) k_main(
    const float* __restrict__ recon, const float* __restrict__ gt,
    const float* __restrict__ obj)
{
    __shared__ __align__(16) u64 T[PRIOR_PAD][4];
    __shared__ __align__(8) float2 s_cm[8][FUS_SEGLEN];   // per-warp {col-min recon, gt}
    const int tid = threadIdx.x;
    const int lane = tid & 31, warp = tid >> 5;
    const float FINF = __int_as_float(0x7F800000);
    const int item = blockIdx.x;

    if (item >= PRIOR_ITEMS) {
        // ===== FUSED: row argmin (obj->hand) + col min (hand->obj) =====
        const int fit   = item - PRIOR_ITEMS;
        const int seg   = fit & 7;
        const int rest  = fit >> 3;
        const int chunk = rest % FUS_CHUNKS;
        const int b     = rest / FUS_CHUNKS;
        const int j0 = chunk * 512 + tid;
        const int j1 = j0 + 256;
        const bool a0 = (j0 < NO), a1 = (j1 < NO);
        const int jj0 = a0 ? j0 : (NO - 1);
        const int jj1 = a1 ? j1 : (NO - 1);

        const float* ob = obj + (size_t)b * NO * 3;
        const float ox0 = ob[3*jj0], oy0 = ob[3*jj0+1], oz0 = ob[3*jj0+2];
        const float ox1 = ob[3*jj1], oy1 = ob[3*jj1+1], oz1 = ob[3*jj1+2];
        const float bq0 = 0.5f*(ox0*ox0 + oy0*oy0 + oz0*oz0);
        const float bq1 = 0.5f*(ox1*ox1 + oy1*oy1 + oz1*oz1);

        const u64 BQ0 = pack2(bq0, bq0), NX0 = pack2(-ox0, -ox0),
                  NY0 = pack2(-oy0, -oy0), NZ0 = pack2(-oz0, -oz0);
        const u64 BQ1 = pack2(bq1, bq1), NX1 = pack2(-ox1, -ox1),
                  NY1 = pack2(-oy1, -oy1), NZ1 = pack2(-oz1, -oz1);

        const float* rb = recon + (size_t)b * NH * 3;
        const float* gb = gt    + (size_t)b * NH * 3;
        const int t0 = seg * FUS_SEGLEN;

        if (tid < FUS_SEGLEN) {
            const int tg = t0 + tid;
            float rx=0.f, ry=0.f, rz=0.f, rw=FINF, gx=0.f, gy=0.f, gz=0.f, gw=FINF;
            if (tg < NH) {
                rx = rb[3*tg]; ry = rb[3*tg+1]; rz = rb[3*tg+2];
                rw = 0.5f*(rx*rx + ry*ry + rz*rz);
                gx = gb[3*tg]; gy = gb[3*tg+1]; gz = gb[3*tg+2];
                gw = 0.5f*(gx*gx + gy*gy + gz*gz);
            }
            float2* pp = (float2*)T[tid];
            pp[0] = make_float2(rx, gx); pp[1] = make_float2(ry, gy);
            pp[2] = make_float2(rz, gz); pp[3] = make_float2(rw, gw);
        }
        __syncthreads();

        unsigned br0 = 0xFFFFFFFFu, bg0 = 0xFFFFFFFFu;
        unsigned br1 = 0xFFFFFFFFu, bg1 = 0xFFFFFFFFu;
#pragma unroll 4
        for (int k = 0; k < FUS_SEGLEN; k++) {
            const ulonglong2 A  = *(const ulonglong2*)&T[k][0];
            const ulonglong2 Bv = *(const ulonglong2*)&T[k][2];
            const unsigned kb = (unsigned)(t0 + k);
            u64 M0 = add2(BQ0, Bv.y);
            M0 = fma2(NX0, A.x, M0); M0 = fma2(NY0, A.y, M0); M0 = fma2(NZ0, Bv.x, M0);
            unsigned r0, g0; unpack2u(M0, r0, g0);
            br0 = min(br0, (r0 & 0xFFFFFC00u) | kb);
            bg0 = min(bg0, (g0 & 0xFFFFFC00u) | kb);
            u64 M1 = add2(BQ1, Bv.y);
            M1 = fma2(NX1, A.x, M1); M1 = fma2(NY1, A.y, M1); M1 = fma2(NZ1, Bv.x, M1);
            unsigned r1, g1; unpack2u(M1, r1, g1);
            br1 = min(br1, (r1 & 0xFFFFFC00u) | kb);
            bg1 = min(bg1, (g1 & 0xFFFFFC00u) | kb);
            float vr = fmaxf(fminf(__uint_as_float(r0), __uint_as_float(r1)), 0.f);
            float vg = fmaxf(fminf(__uint_as_float(g0), __uint_as_float(g1)), 0.f);
            unsigned wr = __reduce_min_sync(0xffffffffu, __float_as_uint(vr));
            unsigned wg = __reduce_min_sync(0xffffffffu, __float_as_uint(vg));
            if (lane == 0)
                s_cm[warp][k] = make_float2(__uint_as_float(wr), __uint_as_float(wg));
        }
        if (a0) { g_okr[seg][b * NO + j0] = br0; g_okg[seg][b * NO + j0] = bg0; }
        if (a1) { g_okr[seg][b * NO + j1] = br1; g_okg[seg][b * NO + j1] = bg1; }

        __syncthreads();
        if (tid < FUS_SEGLEN) {
            float2 m = s_cm[0][tid];
#pragma unroll
            for (int w = 1; w < 8; w++) {
                float2 v = s_cm[w][tid];
                m.x = fminf(m.x, v.x);
                m.y = fminf(m.y, v.y);
            }
            g_cmr[chunk][b * NT_PAD + t0 + tid] = m.x;
            g_cmg[chunk][b * NT_PAD + t0 + tid] = m.y;
        }
    } else {
        // ===== PRIOR: 204 targets, 512 queries (longest blocks -> lowest bids) =====
        const int idx   = item;
        const int chunk = idx % FUS_CHUNKS;
        const int b     = idx / FUS_CHUNKS;
        const int j0 = chunk * 512 + tid;
        const int j1 = j0 + 256;
        const bool a0 = (j0 < NO), a1 = (j1 < NO);
        const int jj0 = a0 ? j0 : (NO - 1);
        const int jj1 = a1 ? j1 : (NO - 1);

        const float* ob = obj + (size_t)b * NO * 3;
        const float ox0 = ob[3*jj0], oy0 = ob[3*jj0+1], oz0 = ob[3*jj0+2];
        const float ox1 = ob[3*jj1], oy1 = ob[3*jj1+1], oz1 = ob[3*jj1+2];
        const float bq0 = 0.5f*(ox0*ox0 + oy0*oy0 + oz0*oz0);
        const float bq1 = 0.5f*(ox1*ox1 + oy1*oy1 + oz1*oz1);
        const u64 BQP = pack2(bq0, bq1), NXP = pack2(-ox0, -ox1),
                  NYP = pack2(-oy0, -oy1), NZP = pack2(-oz0, -oz1);

        const float* rb = recon + (size_t)b * NH * 3;
        if (tid < PRIOR_PAD) {
            float x = 0.f, y = 0.f, z = 0.f, w = FINF;
            if (tid < NPRIOR) {
                const int p = c_prior[tid];
                x = rb[3*p]; y = rb[3*p+1]; z = rb[3*p+2];
                w = 0.5f*(x*x + y*y + z*z);
            }
            float2* pp = (float2*)T[tid];
            pp[0] = make_float2(x, x); pp[1] = make_float2(y, y);
            pp[2] = make_float2(z, z); pp[3] = make_float2(w, w);
        }
        __syncthreads();

        float mp0 = FINF, mp1 = FINF;
#pragma unroll 8
        for (int k = 0; k < PRIOR_PAD; k++) {
            const ulonglong2 A  = *(const ulonglong2*)&T[k][0];
            const ulonglong2 Bv = *(const ulonglong2*)&T[k][2];
            u64 M = add2(BQP, Bv.y);
            M = fma2(NXP, A.x, M); M = fma2(NYP, A.y, M); M = fma2(NZP, Bv.x, M);
            unsigned u0, u1; unpack2u(M, u0, u1);
            mp0 = fminf(mp0, __uint_as_float(u0));
            mp1 = fminf(mp1, __uint_as_float(u1));
        }
        if (a0) g_mp[b * NO + j0] = mp0;
        if (a1) g_mp[b * NO + j1] = mp1;
    }
}

// Epilogue: PDL secondary. MSE/KLD blocks (no dependence on k_main) come first
// and skip the grid-dependency sync; OBJ/HAND blocks sync before reading.
__global__ void __launch_bounds__(256) k_epi(
    const float* __restrict__ recon, const float* __restrict__ gt,
    const float* __restrict__ recon_n, const float* __restrict__ gt_n,
    const float* __restrict__ obj,
    const float* __restrict__ mean, const float* __restrict__ logv,
    const float* __restrict__ vw, float* __restrict__ out)
{
    const int tid = threadIdx.x;
    const int blk = blockIdx.x;

    float a[8] = {0.f,0.f,0.f,0.f,0.f,0.f,0.f,0.f};

    if (blk < EPI_MSE_BLOCKS) {
        const int q = blk * 256 + tid;
        if (q < (B_ * NH * 3) / 4) {
            const float4 r4 = ((const float4*)recon)[q];
            const float4 g4 = ((const float4*)gt)[q];
            float d0 = r4.x - g4.x, d1 = r4.y - g4.y, d2 = r4.z - g4.z, d3 = r4.w - g4.w;
            a[6] = d0*d0 + d1*d1 + d2*d2 + d3*d3;
        }
    } else if (blk < EPI_MSE_BLOCKS + EPI_KLD_BLOCKS) {
        const int q = (blk - EPI_MSE_BLOCKS) * 256 + tid;
        float m = mean[q], lv = logv[q];
        a[7] = 1.f + lv - m * m - expf(lv);
    } else if (blk < EPI_MSE_BLOCKS + EPI_KLD_BLOCKS + EPI_OBJ_BLOCKS) {
        cudaGridDependencySynchronize();
        const int idx = (blk - EPI_MSE_BLOCKS - EPI_KLD_BLOCKS) * 256 + tid;
        const int b = idx / NO;
        const int j = idx - b * NO;
        const float* ob = obj + (size_t)b * NO * 3;
        const float ox = ob[3*j], oy = ob[3*j+1], oz = ob[3*j+2];
        unsigned br = g_okr[0][idx], bg = g_okg[0][idx];
#pragma unroll
        for (int s = 1; s < FUS_SEGS; s++) {
            br = min(br, g_okr[s][idx]);
            bg = min(bg, g_okg[s][idx]);
        }
        const int ir = (int)(br & 1023u);
        const int ig = (int)(bg & 1023u);
        const float mp = g_mp[idx];

        const float* rb  = recon   + (size_t)b * NH * 3;
        const float* gb  = gt      + (size_t)b * NH * 3;
        const float* rnb = recon_n + (size_t)b * NH * 3;
        const float* gnb = gt_n    + (size_t)b * NH * 3;

        float dxr = ox - rb[3*ir], dyr = oy - rb[3*ir+1], dzr = oz - rb[3*ir+2];
        float d2r = dxr*dxr + dyr*dyr + dzr*dzr;
        float dotr = rnb[3*ir]*dxr + rnb[3*ir+1]*dyr + rnb[3*ir+2]*dzr;
        float o2h = sqrtf(d2r) * sgnf(dotr);
        bool interior = (-dotr) > 0.f;

        float dxg = ox - gb[3*ig], dyg = oy - gb[3*ig+1], dzg = oz - gb[3*ig+2];
        float d2g = dxg*dxg + dyg*dyg + dzg*dzg;
        float dotg = gnb[3*ig]*dxg + gnb[3*ig+1]*dyg + gnb[3*ig+2]*dzg;
        float o2h_gt = sqrtf(d2g) * sgnf(dotg);

        float d2p = fmaxf(2.f * mp, 0.f);
        bool cmap  = sqrtf(d2g) < 0.005f;
        bool rcmap = sqrtf(d2r) < 0.005f;

        a[0] = interior ? d2r : 0.f;
        a[1] = cmap ? 1.f : 0.f;
        a[2] = cmap ? d2p : 0.f;
        a[3] = (cmap && rcmap) ? 1.f : 0.f;
        bool w_dist = (o2h_gt < 0.01f) && (o2h_gt > -0.005f);
        float w = (o2h < 0.f) ? 1.5f : (w_dist ? 1.0f : 0.1f);
        a[4] = fabsf(o2h - o2h_gt) * w;
    } else {
        cudaGridDependencySynchronize();
        const int j = (blk - EPI_MSE_BLOCKS - EPI_KLD_BLOCKS - EPI_OBJ_BLOCKS) * 256 + tid;
        if (j < B_ * NH) {
            const int b = j / NH;
            const int i = j - b * NH;
            const int base = b * NT_PAD + i;
            float mr = g_cmr[0][base], mg = g_cmg[0][base];
#pragma unroll
            for (int c = 1; c < FUS_CHUNKS; c++) {
                mr = fminf(mr, g_cmr[c][base]);
                mg = fminf(mg, g_cmg[c][base]);
            }
            float dr = sqrtf(fmaxf(2.f * mr, 0.f));
            float dg = sqrtf(fmaxf(2.f * mg, 0.f));
            a[5] = fabsf(dr - dg) * powf(vw[i], 0.4f);
        }
    }

    __shared__ float red[8][8];
    __shared__ bool s_last;
    const int lane = tid & 31, warp = tid >> 5;
#pragma unroll
    for (int q = 0; q < 8; q++) {
        float v = warp_sum(a[q]);
        if (lane == 0) red[warp][q] = v;
    }
    __syncthreads();
    if (tid < 8) {
        float s = 0.f;
#pragma unroll
        for (int wi = 0; wi < 8; wi++) s += red[wi][tid];
        g_epart[blk][tid] = s;
    }
    if (tid == 0) {
        __threadfence();
        unsigned t = atomicAdd(&g_ctr, 1u);
        s_last = (t == (unsigned)(gridDim.x - 1));
    }
    __syncthreads();

    if (s_last) {
        __threadfence();
        float p[8] = {0.f,0.f,0.f,0.f,0.f,0.f,0.f,0.f};
        for (int i = tid; i < EPI_TOTAL; i += 256) {
#pragma unroll
            for (int q = 0; q < 8; q++) p[q] += g_epart[i][q];
        }
#pragma unroll
        for (int q = 0; q < 8; q++) {
            float v = warp_sum(p[q]);
            if (lane == 0) red[warp][q] = v;
        }
        __syncthreads();
        if (tid == 0) {
            double acc[8];
#pragma unroll
            for (int q = 0; q < 8; q++) {
                float s = 0.f;
                for (int wi = 0; wi < 8; wi++) s += red[wi][q];
                acc[q] = (double)s;
            }
            const double KLC = 0.005;
            double recon_loss = acc[6] / B_;
            double kld        = -0.5 * acc[7] / B_ * 10.0;
            double penetr     = 100.0 * acc[0] / B_;
            double npts       = acc[1];
            double contact    = 3000.0 * ((npts > 0.0) ? (acc[2] / (B_ * npts)) : 0.0);
            double consist    = -5.0 * acc[3] / (npts + 0.0001);
            double loss_o     = 30.0 * (1.0 - KLC) * acc[4] / ((double)B_ * NO);
            double loss_h     = 35.0 * (1.0 - KLC) * acc[5] / ((double)B_ * NH);
            double total = recon_loss + 0.1 * kld + 1000.0 * penetr
                         + 10.0 * contact + 10.0 * consist + (loss_h + loss_o);
            out[0] = (float)total;
            g_ctr = 0u;
        }
    }
}

extern "C" void kernel_launch(void* const* d_in, const int* in_sizes, int n_in,
                              void* d_out, int out_size) {
    const float* recon   = (const float*)d_in[0];
    const float* gt      = (const float*)d_in[1];
    const float* recon_n = (const float*)d_in[2];
    const float* gt_n    = (const float*)d_in[3];
    const float* obj     = (const float*)d_in[4];
    const float* mean    = (const float*)d_in[5];
    const float* logv    = (const float*)d_in[6];
    const float* vw      = (const float*)d_in[7];
    float* out = (float*)d_out;

    k_main<<<TOTAL_ITEMS, 256>>>(recon, gt, obj);

    // PDL: k_epi launches early; dependent blocks gate on cudaGridDependencySynchronize.
    cudaLaunchConfig_t cfg = {};
    cfg.gridDim  = dim3(EPI_TOTAL, 1, 1);
    cfg.blockDim = dim3(256, 1, 1);
    cudaLaunchAttribute attrs[1];
    attrs[0].id = cudaLaunchAttributeProgrammaticStreamSerialization;
    attrs[0].val.programmaticStreamSerializationAllowed = 1;
    cfg.attrs = attrs;
    cfg.numAttrs = 1;
    cudaLaunchKernelEx(&cfg, k_epi, recon, gt, recon_n, gt_n, obj, mean, logv, vw, out);
}

// round 11
// speedup vs baseline: 1.2902x; 1.0376x over previous
#include <cuda_runtime.h>
#include <math.h>

#define B_  32
#define NH  778
#define NO  3000
#define Z_  64
#define NPRIOR 204

#define NT_PAD      800
#define FUS_SEGS    8
#define FUS_SEGLEN  100
#define FUS_CHUNKS  6          // 6*512 = 3072 >= 3000 (2 queries/thread)
#define FUS_ITEMS   (FUS_SEGS * FUS_CHUNKS * B_)    // 1536
#define PRIOR_PAD   208
#define PRIOR_ITEMS (FUS_CHUNKS * B_)               // 192 (first: longest blocks)
#define TOTAL_ITEMS (FUS_ITEMS + PRIOR_ITEMS)       // 1728

#define EPI_MSE_BLOCKS  73
#define EPI_KLD_BLOCKS  8
#define EPI_OBJ_BLOCKS  375
#define EPI_HAND_BLOCKS 98
#define EPI_TOTAL (EPI_MSE_BLOCKS + EPI_KLD_BLOCKS + EPI_OBJ_BLOCKS + EPI_HAND_BLOCKS) // 554

// Merged via atomicMax(~bits): zero-initialized at module load = identity;
// k_epi resets slots to 0 after consuming -> graph-replay deterministic.
__device__ unsigned g_okr[B_ * NO];      // ~(obj->recon argmin key)
__device__ unsigned g_okg[B_ * NO];      // ~(obj->gt argmin key)
__device__ float    g_mp[B_ * NO];       // plain store (single writer)
__device__ unsigned g_cmr[B_ * NT_PAD];  // ~(col-min bits, recon)
__device__ unsigned g_cmg[B_ * NT_PAD];  // ~(col-min bits, gt)
__device__ float    g_epart[EPI_TOTAL][8];
__device__ unsigned g_ctr;

__constant__ int c_prior[NPRIOR] = {
  697,698,699,700,712,713,714,715,737,738,739,740,741,743,744,745,
  746,748,749,750,753,754,755,756,757,758,759,760,761,762,763,764,
  765,766,767,768,
  46,47,48,49,164,165,166,167,194,195,223,237,238,280,281,298,
  301,317,320,323,324,325,326,327,328,329,330,331,332,333,340,341,
  342,343,344,345,346,347,348,349,350,351,352,353,354,355,
  356,357,358,359,375,376,386,387,396,397,402,403,413,429,433,434,
  435,436,437,438,439,440,441,442,443,444,452,453,454,455,456,459,
  460,461,462,463,464,465,466,467,
  468,469,470,471,484,485,486,496,497,506,507,513,514,524,545,546,
  547,548,549,550,551,552,553,555,563,564,565,566,567,570,572,573,
  574,575,576,577,578,
  580,581,582,583,600,601,602,614,615,624,625,630,631,641,663,664,
  665,666,667,668,670,672,680,681,682,683,684,686,687,688,689,690,
  691,692,693,694,695,
  73,96,98,99,772,774,775,777
};

typedef unsigned long long u64;

__device__ __forceinline__ u64 fma2(u64 a, u64 b, u64 c) {
    u64 d;
    asm("fma.rn.f32x2 %0, %1, %2, %3;" : "=l"(d) : "l"(a), "l"(b), "l"(c));
    return d;
}
__device__ __forceinline__ u64 add2(u64 a, u64 b) {
    u64 d;
    asm("add.rn.f32x2 %0, %1, %2;" : "=l"(d) : "l"(a), "l"(b));
    return d;
}
__device__ __forceinline__ u64 pack2(float lo, float hi) {
    u64 d;
    asm("mov.b64 %0, {%1, %2};" : "=l"(d) : "r"(__float_as_uint(lo)), "r"(__float_as_uint(hi)));
    return d;
}
__device__ __forceinline__ void unpack2u(u64 v, unsigned& lo, unsigned& hi) {
    asm("mov.b64 {%0, %1}, %2;" : "=r"(lo), "=r"(hi) : "l"(v));
}
__device__ __forceinline__ float warp_sum(float v) {
#pragma unroll
    for (int o = 16; o > 0; o >>= 1) v += __shfl_down_sync(0xffffffffu, v, o);
    return v;
}
__device__ __forceinline__ float sgnf(float x) {
    return (x > 0.f) ? 1.f : ((x < 0.f) ? -1.f : 0.f);
}

__global__ void __launch_bounds__(256, 4) k_main(
    const float* __restrict__ recon, const float* __restrict__ gt,
    const float* __restrict__ obj)
{
    __shared__ __align__(16) u64 T[PRIOR_PAD][4];
    __shared__ __align__(8) uint2 s_cm[8][FUS_SEGLEN];   // per-warp col-min bits {recon, gt}
    const int tid = threadIdx.x;
    const int lane = tid & 31, warp = tid >> 5;
    const float FINF = __int_as_float(0x7F800000);
    const int item = blockIdx.x;

    if (item >= PRIOR_ITEMS) {
        // ===== FUSED: row argmin (obj->hand) + col min (hand->obj) =====
        const int fit   = item - PRIOR_ITEMS;
        const int seg   = fit & 7;
        const int rest  = fit >> 3;
        const int chunk = rest % FUS_CHUNKS;
        const int b     = rest / FUS_CHUNKS;
        const int j0 = chunk * 512 + tid;
        const int j1 = j0 + 256;
        const bool a0 = (j0 < NO), a1 = (j1 < NO);
        const int jj0 = a0 ? j0 : (NO - 1);
        const int jj1 = a1 ? j1 : (NO - 1);

        const float* ob = obj + (size_t)b * NO * 3;
        const float ox0 = ob[3*jj0], oy0 = ob[3*jj0+1], oz0 = ob[3*jj0+2];
        const float ox1 = ob[3*jj1], oy1 = ob[3*jj1+1], oz1 = ob[3*jj1+2];
        const float bq0 = 0.5f*(ox0*ox0 + oy0*oy0 + oz0*oz0);
        const float bq1 = 0.5f*(ox1*ox1 + oy1*oy1 + oz1*oz1);

        const u64 BQ0 = pack2(bq0, bq0), NX0 = pack2(-ox0, -ox0),
                  NY0 = pack2(-oy0, -oy0), NZ0 = pack2(-oz0, -oz0);
        const u64 BQ1 = pack2(bq1, bq1), NX1 = pack2(-ox1, -ox1),
                  NY1 = pack2(-oy1, -oy1), NZ1 = pack2(-oz1, -oz1);

        const float* rb = recon + (size_t)b * NH * 3;
        const float* gb = gt    + (size_t)b * NH * 3;
        const int t0 = seg * FUS_SEGLEN;

        if (tid < FUS_SEGLEN) {
            const int tg = t0 + tid;
            float rx=0.f, ry=0.f, rz=0.f, rw=FINF, gx=0.f, gy=0.f, gz=0.f, gw=FINF;
            if (tg < NH) {
                rx = rb[3*tg]; ry = rb[3*tg+1]; rz = rb[3*tg+2];
                rw = 0.5f*(rx*rx + ry*ry + rz*rz);
                gx = gb[3*tg]; gy = gb[3*tg+1]; gz = gb[3*tg+2];
                gw = 0.5f*(gx*gx + gy*gy + gz*gz);
            }
            float2* pp = (float2*)T[tid];
            pp[0] = make_float2(rx, gx); pp[1] = make_float2(ry, gy);
            pp[2] = make_float2(rz, gz); pp[3] = make_float2(rw, gw);
        }
        __syncthreads();

        unsigned br0 = 0xFFFFFFFFu, bg0 = 0xFFFFFFFFu;
        unsigned br1 = 0xFFFFFFFFu, bg1 = 0xFFFFFFFFu;
#pragma unroll 4
        for (int k = 0; k < FUS_SEGLEN; k++) {
            const ulonglong2 A  = *(const ulonglong2*)&T[k][0];
            const ulonglong2 Bv = *(const ulonglong2*)&T[k][2];
            const unsigned kb = (unsigned)(t0 + k);
            u64 M0 = add2(BQ0, Bv.y);
            M0 = fma2(NX0, A.x, M0); M0 = fma2(NY0, A.y, M0); M0 = fma2(NZ0, Bv.x, M0);
            unsigned r0, g0; unpack2u(M0, r0, g0);
            br0 = min(br0, (r0 & 0xFFFFFC00u) | kb);
            bg0 = min(bg0, (g0 & 0xFFFFFC00u) | kb);
            u64 M1 = add2(BQ1, Bv.y);
            M1 = fma2(NX1, A.x, M1); M1 = fma2(NY1, A.y, M1); M1 = fma2(NZ1, Bv.x, M1);
            unsigned r1, g1; unpack2u(M1, r1, g1);
            br1 = min(br1, (r1 & 0xFFFFFC00u) | kb);
            bg1 = min(bg1, (g1 & 0xFFFFFC00u) | kb);
            // col-min on raw positive-float bits (uint order == float order)
            unsigned wr = __reduce_min_sync(0xffffffffu, min(r0, r1));
            unsigned wg = __reduce_min_sync(0xffffffffu, min(g0, g1));
            if (lane == 0) s_cm[warp][k] = make_uint2(wr, wg);
        }
        if (a0) { atomicMax(&g_okr[b * NO + j0], ~br0); atomicMax(&g_okg[b * NO + j0], ~bg0); }
        if (a1) { atomicMax(&g_okr[b * NO + j1], ~br1); atomicMax(&g_okg[b * NO + j1], ~bg1); }

        __syncthreads();
        if (tid < FUS_SEGLEN) {
            uint2 m = s_cm[0][tid];
#pragma unroll
            for (int w = 1; w < 8; w++) {
                uint2 v = s_cm[w][tid];
                m.x = min(m.x, v.x);
                m.y = min(m.y, v.y);
            }
            const int base = b * NT_PAD + t0 + tid;
            atomicMax(&g_cmr[base], ~m.x);
            atomicMax(&g_cmg[base], ~m.y);
        }
    } else {
        // ===== PRIOR: 204 targets, 512 queries =====
        const int idx   = item;
        const int chunk = idx % FUS_CHUNKS;
        const int b     = idx / FUS_CHUNKS;
        const int j0 = chunk * 512 + tid;
        const int j1 = j0 + 256;
        const bool a0 = (j0 < NO), a1 = (j1 < NO);
        const int jj0 = a0 ? j0 : (NO - 1);
        const int jj1 = a1 ? j1 : (NO - 1);

        const float* ob = obj + (size_t)b * NO * 3;
        const float ox0 = ob[3*jj0], oy0 = ob[3*jj0+1], oz0 = ob[3*jj0+2];
        const float ox1 = ob[3*jj1], oy1 = ob[3*jj1+1], oz1 = ob[3*jj1+2];
        const float bq0 = 0.5f*(ox0*ox0 + oy0*oy0 + oz0*oz0);
        const float bq1 = 0.5f*(ox1*ox1 + oy1*oy1 + oz1*oz1);
        const u64 BQP = pack2(bq0, bq1), NXP = pack2(-ox0, -ox1),
                  NYP = pack2(-oy0, -oy1), NZP = pack2(-oz0, -oz1);

        const float* rb = recon + (size_t)b * NH * 3;
        if (tid < PRIOR_PAD) {
            float x = 0.f, y = 0.f, z = 0.f, w = FINF;
            if (tid < NPRIOR) {
                const int p = c_prior[tid];
                x = rb[3*p]; y = rb[3*p+1]; z = rb[3*p+2];
                w = 0.5f*(x*x + y*y + z*z);
            }
            float2* pp = (float2*)T[tid];
            pp[0] = make_float2(x, x); pp[1] = make_float2(y, y);
            pp[2] = make_float2(z, z); pp[3] = make_float2(w, w);
        }
        __syncthreads();

        float mp0 = FINF, mp1 = FINF;
#pragma unroll 8
        for (int k = 0; k < PRIOR_PAD; k++) {
            const ulonglong2 A  = *(const ulonglong2*)&T[k][0];
            const ulonglong2 Bv = *(const ulonglong2*)&T[k][2];
            u64 M = add2(BQP, Bv.y);
            M = fma2(NXP, A.x, M); M = fma2(NYP, A.y, M); M = fma2(NZP, Bv.x, M);
            unsigned u0, u1; unpack2u(M, u0, u1);
            mp0 = fminf(mp0, __uint_as_float(u0));
            mp1 = fminf(mp1, __uint_as_float(u1));
        }
        if (a0) g_mp[b * NO + j0] = mp0;
        if (a1) g_mp[b * NO + j1] = mp1;
    }
}

// Epilogue (PDL secondary): MSE/KLD blocks skip the grid sync; OBJ/HAND sync.
// Consumers reset merged arrays to 0 (identity for atomicMax(~bits)) for replay.
__global__ void __launch_bounds__(256) k_epi(
    const float* __restrict__ recon, const float* __restrict__ gt,
    const float* __restrict__ recon_n, const float* __restrict__ gt_n,
    const float* __restrict__ obj,
    const float* __restrict__ mean, const float* __restrict__ logv,
    const float* __restrict__ vw, float* __restrict__ out)
{
    const int tid = threadIdx.x;
    const int blk = blockIdx.x;

    float a[8] = {0.f,0.f,0.f,0.f,0.f,0.f,0.f,0.f};

    if (blk < EPI_MSE_BLOCKS) {
        const int q = blk * 256 + tid;
        if (q < (B_ * NH * 3) / 4) {
            const float4 r4 = ((const float4*)recon)[q];
            const float4 g4 = ((const float4*)gt)[q];
            float d0 = r4.x - g4.x, d1 = r4.y - g4.y, d2 = r4.z - g4.z, d3 = r4.w - g4.w;
            a[6] = d0*d0 + d1*d1 + d2*d2 + d3*d3;
        }
    } else if (blk < EPI_MSE_BLOCKS + EPI_KLD_BLOCKS) {
        const int q = (blk - EPI_MSE_BLOCKS) * 256 + tid;
        float m = mean[q], lv = logv[q];
        a[7] = 1.f + lv - m * m - expf(lv);
    } else if (blk < EPI_MSE_BLOCKS + EPI_KLD_BLOCKS + EPI_OBJ_BLOCKS) {
        cudaGridDependencySynchronize();
        const int idx = (blk - EPI_MSE_BLOCKS - EPI_KLD_BLOCKS) * 256 + tid;
        const int b = idx / NO;
        const int j = idx - b * NO;
        const unsigned br = ~g_okr[idx];
        const unsigned bg = ~g_okg[idx];
        const float mp = g_mp[idx];
        g_okr[idx] = 0u;
        g_okg[idx] = 0u;

        const float* ob = obj + (size_t)b * NO * 3;
        const float ox = ob[3*j], oy = ob[3*j+1], oz = ob[3*j+2];
        const int ir = (int)(br & 1023u);
        const int ig = (int)(bg & 1023u);

        const float* rb  = recon   + (size_t)b * NH * 3;
        const float* gb  = gt      + (size_t)b * NH * 3;
        const float* rnb = recon_n + (size_t)b * NH * 3;
        const float* gnb = gt_n    + (size_t)b * NH * 3;

        float dxr = ox - rb[3*ir], dyr = oy - rb[3*ir+1], dzr = oz - rb[3*ir+2];
        float d2r = dxr*dxr + dyr*dyr + dzr*dzr;
        float dotr = rnb[3*ir]*dxr + rnb[3*ir+1]*dyr + rnb[3*ir+2]*dzr;
        float o2h = sqrtf(d2r) * sgnf(dotr);
        bool interior = (-dotr) > 0.f;

        float dxg = ox - gb[3*ig], dyg = oy - gb[3*ig+1], dzg = oz - gb[3*ig+2];
        float d2g = dxg*dxg + dyg*dyg + dzg*dzg;
        float dotg = gnb[3*ig]*dxg + gnb[3*ig+1]*dyg + gnb[3*ig+2]*dzg;
        float o2h_gt = sqrtf(d2g) * sgnf(dotg);

        float d2p = fmaxf(2.f * mp, 0.f);
        bool cmap  = sqrtf(d2g) < 0.005f;
        bool rcmap = sqrtf(d2r) < 0.005f;

        a[0] = interior ? d2r : 0.f;
        a[1] = cmap ? 1.f : 0.f;
        a[2] = cmap ? d2p : 0.f;
        a[3] = (cmap && rcmap) ? 1.f : 0.f;
        bool w_dist = (o2h_gt < 0.01f) && (o2h_gt > -0.005f);
        float w = (o2h < 0.f) ? 1.5f : (w_dist ? 1.0f : 0.1f);
        a[4] = fabsf(o2h - o2h_gt) * w;
    } else {
        cudaGridDependencySynchronize();
        const int j = (blk - EPI_MSE_BLOCKS - EPI_KLD_BLOCKS - EPI_OBJ_BLOCKS) * 256 + tid;
        if (j < B_ * NH) {
            const int b = j / NH;
            const int i = j - b * NH;
            const int base = b * NT_PAD + i;
            float mr = __uint_as_float(~g_cmr[base]);
            float mg = __uint_as_float(~g_cmg[base]);
            g_cmr[base] = 0u;
            g_cmg[base] = 0u;
            float dr = sqrtf(fmaxf(2.f * mr, 0.f));
            float dg = sqrtf(fmaxf(2.f * mg, 0.f));
            a[5] = fabsf(dr - dg) * powf(vw[i], 0.4f);
        }
    }

    __shared__ float red[8][8];
    __shared__ bool s_last;
    const int lane = tid & 31, warp = tid >> 5;
#pragma unroll
    for (int q = 0; q < 8; q++) {
        float v = warp_sum(a[q]);
        if (lane == 0) red[warp][q] = v;
    }
    __syncthreads();
    if (tid < 8) {
        float s = 0.f;
#pragma unroll
        for (int wi = 0; wi < 8; wi++) s += red[wi][tid];
        g_epart[blk][tid] = s;
    }
    if (tid == 0) {
        __threadfence();
        unsigned t = atomicAdd(&g_ctr, 1u);
        s_last = (t == (unsigned)(gridDim.x - 1));
    }
    __syncthreads();

    if (s_last) {
        __threadfence();
        float p[8] = {0.f,0.f,0.f,0.f,0.f,0.f,0.f,0.f};
        for (int i = tid; i < EPI_TOTAL; i += 256) {
#pragma unroll
            for (int q = 0; q < 8; q++) p[q] += g_epart[i][q];
        }
#pragma unroll
        for (int q = 0; q < 8; q++) {
            float v = warp_sum(p[q]);
            if (lane == 0) red[warp][q] = v;
        }
        __syncthreads();
        if (tid == 0) {
            double acc[8];
#pragma unroll
            for (int q = 0; q < 8; q++) {
                float s = 0.f;
                for (int wi = 0; wi < 8; wi++) s += red[wi][q];
                acc[q] = (double)s;
            }
            const double KLC = 0.005;
            double recon_loss = acc[6] / B_;
            double kld        = -0.5 * acc[7] / B_ * 10.0;
            double penetr     = 100.0 * acc[0] / B_;
            double npts       = acc[1];
            double contact    = 3000.0 * ((npts > 0.0) ? (acc[2] / (B_ * npts)) : 0.0);
            double consist    = -5.0 * acc[3] / (npts + 0.0001);
            double loss_o     = 30.0 * (1.0 - KLC) * acc[4] / ((double)B_ * NO);
            double loss_h     = 35.0 * (1.0 - KLC) * acc[5] / ((double)B_ * NH);
            double total = recon_loss + 0.1 * kld + 1000.0 * penetr
                         + 10.0 * contact + 10.0 * consist + (loss_h + loss_o);
            out[0] = (float)total;
            g_ctr = 0u;
        }
    }
}

extern "C" void kernel_launch(void* const* d_in, const int* in_sizes, int n_in,
                              void* d_out, int out_size) {
    const float* recon   = (const float*)d_in[0];
    const float* gt      = (const float*)d_in[1];
    const float* recon_n = (const float*)d_in[2];
    const float* gt_n    = (const float*)d_in[3];
    const float* obj     = (const float*)d_in[4];
    const float* mean    = (const float*)d_in[5];
    const float* logv    = (const float*)d_in[6];
    const float* vw      = (const float*)d_in[7];
    float* out = (float*)d_out;

    k_main<<<TOTAL_ITEMS, 256>>>(recon, gt, obj);

    cudaLaunchConfig_t cfg = {};
    cfg.gridDim  = dim3(EPI_TOTAL, 1, 1);
    cfg.blockDim = dim3(256, 1, 1);
    cudaLaunchAttribute attrs[1];
    attrs[0].id = cudaLaunchAttributeProgrammaticStreamSerialization;
    attrs[0].val.programmaticStreamSerializationAllowed = 1;
    cfg.attrs = attrs;
    cfg.numAttrs = 1;
    cudaLaunchKernelEx(&cfg, k_epi, recon, gt, recon_n, gt_n, obj, mean, logv, vw, out);
}